// round 14
// baseline (speedup 1.0000x reference)
#include <cuda_runtime.h>
#include <cuda_bf16.h>
#include <cstdint>

#define NN 100000
#define EE 3200000
#define RR 20
#define DD 64
#define NR (NN * RR)
#define SCAN_ELEMS 2048
#define SCAN_BLKS ((NR + SCAN_ELEMS - 1) / SCAN_ELEMS)

#define TILE_M 128
#define NTILES ((NN + TILE_M - 1) / TILE_M)   // 782
#define APAD 72
#define A_BYTES (TILE_M * APAD * 2)           // 18432
#define B_BYTES (64 * APAD * 2)               // 9216
#define NOFF (TILE_M * RR)                    // 2560 buckets per tile
#define ECAP 6144                             // staged edge capacity (24 KB)
#define SMEM_LAYER (2 * A_BYTES + 2 * B_BYTES + (NOFF + 4) * 4 + ECAP * 4)

// ---------------- scratch ----------------
__device__ float g_h1[(size_t)NN * DD];
__device__ int   g_cnt2[NR];
__device__ int   g_cursor2[NR];
__device__ int   g_rowoff2[NR + 1];
__device__ int   g_part[1024];
__device__ int   g_sorted[EE];
__device__ float g_gsum[DD];
__device__ __nv_bfloat16 g_Bhi[2][RR * 64 * APAD];
__device__ __nv_bfloat16 g_Blo[2][RR * 64 * APAD];

// ---------------- prep: counting sort by (dst*RR + etype) ----------------
__global__ void zero2_kernel() {
    int i = blockIdx.x * blockDim.x + threadIdx.x;
    int stride = gridDim.x * blockDim.x;
    for (; i < NR; i += stride) g_cnt2[i] = 0;
    if (blockIdx.x == 0 && threadIdx.x < DD) g_gsum[threadIdx.x] = 0.0f;
}
__global__ void count2_kernel(const int* __restrict__ dst, const int* __restrict__ et) {
    int i = blockIdx.x * blockDim.x + threadIdx.x;
    int stride = gridDim.x * blockDim.x;
    for (; i < EE; i += stride) atomicAdd(&g_cnt2[dst[i] * RR + et[i]], 1);
}
__global__ __launch_bounds__(1024) void scanA_kernel() {
    __shared__ int wsum[32];
    const int tid = threadIdx.x, lane = tid & 31, wid = tid >> 5;
    int i0 = blockIdx.x * SCAN_ELEMS + tid * 2;
    int v0 = (i0 < NR) ? g_cnt2[i0] : 0;
    int v1 = (i0 + 1 < NR) ? g_cnt2[i0 + 1] : 0;
    int tsum = v0 + v1, x = tsum;
    #pragma unroll
    for (int off = 1; off < 32; off <<= 1) {
        int y = __shfl_up_sync(0xFFFFFFFFu, x, off);
        if (lane >= off) x += y;
    }
    if (lane == 31) wsum[wid] = x;
    __syncthreads();
    if (wid == 0) {
        int w = wsum[lane];
        #pragma unroll
        for (int off = 1; off < 32; off <<= 1) {
            int y = __shfl_up_sync(0xFFFFFFFFu, w, off);
            if (lane >= off) w += y;
        }
        wsum[lane] = w;
    }
    __syncthreads();
    int excl = x - tsum + (wid ? wsum[wid - 1] : 0);
    if (i0 < NR) g_rowoff2[i0] = excl;
    if (i0 + 1 < NR) g_rowoff2[i0 + 1] = excl + v0;
    if (tid == 0) g_part[blockIdx.x] = wsum[31];
}
__global__ __launch_bounds__(1024) void scanB_kernel() {
    __shared__ int wsum[32];
    const int tid = threadIdx.x, lane = tid & 31, wid = tid >> 5;
    int v = (tid < SCAN_BLKS) ? g_part[tid] : 0;
    int x = v;
    #pragma unroll
    for (int off = 1; off < 32; off <<= 1) {
        int y = __shfl_up_sync(0xFFFFFFFFu, x, off);
        if (lane >= off) x += y;
    }
    if (lane == 31) wsum[wid] = x;
    __syncthreads();
    if (wid == 0) {
        int w = wsum[lane];
        #pragma unroll
        for (int off = 1; off < 32; off <<= 1) {
            int y = __shfl_up_sync(0xFFFFFFFFu, w, off);
            if (lane >= off) w += y;
        }
        wsum[lane] = w;
    }
    __syncthreads();
    g_part[tid] = x - v + (wid ? wsum[wid - 1] : 0);
}
__global__ void scanC_kernel() {
    int i = blockIdx.x * blockDim.x + threadIdx.x;
    int stride = gridDim.x * blockDim.x;
    for (; i < NR; i += stride) {
        int v = g_rowoff2[i] + g_part[i >> 11];
        g_rowoff2[i] = v;
        g_cursor2[i] = v;
    }
    if (blockIdx.x == 0 && threadIdx.x == 0) g_rowoff2[NR] = EE;
}
__global__ void scatter2_kernel(const int* __restrict__ src,
                                const int* __restrict__ dst,
                                const int* __restrict__ et) {
    int i = blockIdx.x * blockDim.x + threadIdx.x;
    int stride = gridDim.x * blockDim.x;
    for (; i < EE; i += stride) {
        int pos = atomicAdd(&g_cursor2[dst[i] * RR + et[i]], 1);
        g_sorted[pos] = src[i];
    }
}

// ---------------- W prep: transpose + bf16 hi/lo split ----------------
__global__ void wprep_kernel(const float* __restrict__ W, int slot) {
    int r = blockIdx.x;
    for (int idx = threadIdx.x; idx < 4096; idx += blockDim.x) {
        int o = idx >> 6, d = idx & 63;
        float v = W[r * 4096 + d * 64 + o];
        __nv_bfloat16 hi = __float2bfloat16(v);
        float rest = v - __bfloat162float(hi);
        g_Bhi[slot][r * 64 * APAD + o * APAD + d] = hi;
        g_Blo[slot][r * 64 * APAD + o * APAD + d] = __float2bfloat16(rest);
    }
}

// ---------------- fused layer ----------------
static __device__ __forceinline__ void mma_bf16(float* c, const uint32_t* a, const uint32_t* b) {
    asm volatile(
        "mma.sync.aligned.m16n8k16.row.col.f32.bf16.bf16.f32 "
        "{%0,%1,%2,%3}, {%4,%5,%6,%7}, {%8,%9}, {%0,%1,%2,%3};"
        : "+f"(c[0]), "+f"(c[1]), "+f"(c[2]), "+f"(c[3])
        : "r"(a[0]), "r"(a[1]), "r"(a[2]), "r"(a[3]), "r"(b[0]), "r"(b[1]));
}

__global__ void __launch_bounds__(256, 2)
layer_kernel(const float* __restrict__ in, int slot, float* __restrict__ out, int relu) {
    extern __shared__ __align__(16) char sm[];
    char* AH = sm;                                   // [128][APAD] bf16
    char* AL = AH + A_BYTES;
    char* BH = AL + A_BYTES;                         // [64][APAD] bf16 (W^T)
    char* BL = BH + B_BYTES;
    int*  s_off  = (int*)(BL + B_BYTES);             // NOFF+1 global bucket offsets
    int*  s_edge = s_off + NOFF + 4;                 // staged src indices (<= ECAP)

    const int tid = threadIdx.x;
    const int node0 = blockIdx.x * TILE_M;
    const int hw = tid >> 4;       // 0..15 half-warp
    const int l4 = tid & 15;       // feature quad
    const int wid = tid >> 5;      // 0..7
    const int lane = tid & 31;
    const int g = lane >> 2;       // 0..7
    const int tg = lane & 3;       // 0..3
    const int R0 = wid * 16;

    // ---- stage bucket offsets (coalesced) ----
    const int key0 = node0 * RR;
    for (int i = tid; i <= NOFF; i += 256) {
        int k = key0 + i;
        s_off[i] = g_rowoff2[(k < NR) ? k : NR];
    }
    __syncthreads();
    const int base = s_off[0];
    const int ecnt = s_off[NOFF] - base;
    // ---- stage edge list (coalesced), cap at ECAP ----
    {
        int lim = (ecnt < ECAP) ? ecnt : ECAP;
        for (int i = tid; i < lim; i += 256) s_edge[i] = g_sorted[base + i];
    }

    float c[8][4];
    #pragma unroll
    for (int i = 0; i < 8; i++)
        #pragma unroll
        for (int j = 0; j < 4; j++) c[i][j] = 0.f;

    const __nv_bfloat16* Bh = g_Bhi[slot];
    const __nv_bfloat16* Bl = g_Blo[slot];
    __syncthreads();

    for (int r = 0; r < RR; r++) {
        // ---- B copy ----
        {
            const uint4* bs = (const uint4*)(Bh + (size_t)r * 64 * APAD);
            const uint4* ls = (const uint4*)(Bl + (size_t)r * 64 * APAD);
            uint4* bd = (uint4*)BH;
            uint4* ld = (uint4*)BL;
            for (int i = tid; i < 576; i += 256) { bd[i] = bs[i]; ld[i] = ls[i]; }
        }
        // ---- gather: half-warp per node, 8 buckets, indices from smem ----
        #pragma unroll
        for (int p = 0; p < 8; p++) {
            int nn = hw + p * 16;
            int s = s_off[nn * RR + r] - base;
            int e = s_off[nn * RR + r + 1] - base;
            float4 acc = make_float4(0.f, 0.f, 0.f, 0.f);
            for (int i = s; i < e; i++) {
                int sv = (i < ECAP) ? s_edge[i] : g_sorted[base + i];
                const float4 v = *(const float4*)(in + (size_t)sv * 64 + l4 * 4);
                acc.x += v.x; acc.y += v.y; acc.z += v.z; acc.w += v.w;
            }
            __nv_bfloat162 h01 = __floats2bfloat162_rn(acc.x, acc.y);
            __nv_bfloat162 h23 = __floats2bfloat162_rn(acc.z, acc.w);
            float2 f01 = __bfloat1622float2(h01);
            float2 f23 = __bfloat1622float2(h23);
            __nv_bfloat162 l01 = __floats2bfloat162_rn(acc.x - f01.x, acc.y - f01.y);
            __nv_bfloat162 l23 = __floats2bfloat162_rn(acc.z - f23.x, acc.w - f23.y);
            uint32_t off = (uint32_t)(nn * APAD + l4 * 4) * 2;
            *(uint2*)(AH + off) = make_uint2(*(uint32_t*)&h01, *(uint32_t*)&h23);
            *(uint2*)(AL + off) = make_uint2(*(uint32_t*)&l01, *(uint32_t*)&l23);
        }
        __syncthreads();

        // ---- MMA: warp computes rows [R0, R0+16) x 64 cols ----
        #pragma unroll
        for (int kc = 0; kc < 4; kc++) {
            const int kb = kc * 16;
            uint32_t ah[4], al[4];
            {
                uint32_t o0 = (uint32_t)((R0 + g) * APAD + kb + tg * 2) * 2;
                uint32_t o1 = (uint32_t)((R0 + g + 8) * APAD + kb + tg * 2) * 2;
                ah[0] = *(const uint32_t*)(AH + o0);
                ah[1] = *(const uint32_t*)(AH + o1);
                ah[2] = *(const uint32_t*)(AH + o0 + 16);
                ah[3] = *(const uint32_t*)(AH + o1 + 16);
                al[0] = *(const uint32_t*)(AL + o0);
                al[1] = *(const uint32_t*)(AL + o1);
                al[2] = *(const uint32_t*)(AL + o0 + 16);
                al[3] = *(const uint32_t*)(AL + o1 + 16);
            }
            #pragma unroll
            for (int nt = 0; nt < 8; nt++) {
                uint32_t bh[2], bl[2];
                uint32_t ob = (uint32_t)((nt * 8 + g) * APAD + kb + tg * 2) * 2;
                bh[0] = *(const uint32_t*)(BH + ob);
                bh[1] = *(const uint32_t*)(BH + ob + 16);
                bl[0] = *(const uint32_t*)(BL + ob);
                bl[1] = *(const uint32_t*)(BL + ob + 16);
                mma_bf16(c[nt], ah, bh);
                mma_bf16(c[nt], ah, bl);
                mma_bf16(c[nt], al, bh);
            }
        }
        __syncthreads();
    }

    // ---- epilogue ----
    int row_a = node0 + R0 + g;
    int row_b = row_a + 8;
    #pragma unroll
    for (int nt = 0; nt < 8; nt++) {
        float v0 = c[nt][0], v1 = c[nt][1], v2 = c[nt][2], v3 = c[nt][3];
        if (relu) {
            v0 = fmaxf(v0, 0.f); v1 = fmaxf(v1, 0.f);
            v2 = fmaxf(v2, 0.f); v3 = fmaxf(v3, 0.f);
        }
        int col = nt * 8 + tg * 2;
        if (row_a < NN) *(float2*)(out + (size_t)row_a * 64 + col) = make_float2(v0, v1);
        if (row_b < NN) *(float2*)(out + (size_t)row_b * 64 + col) = make_float2(v2, v3);
    }
}

// ---------------- graph mean + attributor MLP ----------------
__global__ void mean_kernel(const float* __restrict__ h2) {
    int dim = threadIdx.x & 63;
    int rgrp = threadIdx.x >> 6;
    float acc = 0.f;
    for (int row = blockIdx.x * 4 + rgrp; row < NN; row += gridDim.x * 4)
        acc += h2[(size_t)row * 64 + dim];
    __shared__ float s[256];
    s[threadIdx.x] = acc;
    __syncthreads();
    if (threadIdx.x < 64) {
        float v = s[threadIdx.x] + s[threadIdx.x + 64] + s[threadIdx.x + 128] + s[threadIdx.x + 192];
        atomicAdd(&g_gsum[threadIdx.x], v);
    }
}
__global__ void mlp_kernel(const float* __restrict__ A1w, const float* __restrict__ A1b,
                           const float* __restrict__ A2w, const float* __restrict__ A2b,
                           float* __restrict__ out) {
    __shared__ float g[64];
    __shared__ float hid[32];
    int tid = threadIdx.x;
    if (tid < 64) g[tid] = g_gsum[tid] * (1.0f / (float)NN);
    __syncthreads();
    if (tid < 32) {
        float s = A1b[tid];
        #pragma unroll
        for (int k = 0; k < 64; k++) s += g[k] * A1w[k * 32 + tid];
        hid[tid] = fmaxf(s, 0.f);
    }
    __syncthreads();
    if (tid < 10) {
        float s = A2b[tid];
        #pragma unroll
        for (int k = 0; k < 32; k++) s += hid[k] * A2w[k * 10 + tid];
        out[(size_t)NN * 64 + tid] = 1.0f / (1.0f + expf(-s));
    }
}

// ---------------- launch ----------------
extern "C" void kernel_launch(void* const* d_in, const int* in_sizes, int n_in,
                              void* d_out, int out_size) {
    const float* h   = (const float*)d_in[0];
    const int*   src = (const int*)d_in[1];
    const int*   dst = (const int*)d_in[2];
    const int*   et  = (const int*)d_in[3];
    const float* W1  = (const float*)d_in[4];
    const float* W2  = (const float*)d_in[5];
    const float* A1w = (const float*)d_in[6];
    const float* A1b = (const float*)d_in[7];
    const float* A2w = (const float*)d_in[8];
    const float* A2b = (const float*)d_in[9];
    float* out = (float*)d_out;

    void* h1_ptr = nullptr;
    cudaGetSymbolAddress(&h1_ptr, g_h1);
    float* h1 = (float*)h1_ptr;

    static bool attr_done = false;
    if (!attr_done) {
        cudaFuncSetAttribute(layer_kernel, cudaFuncAttributeMaxDynamicSharedMemorySize, SMEM_LAYER);
        attr_done = true;
    }

    const int TB = 256;
    const int edge_blocks = (EE + TB - 1) / TB;
    const int nr_blocks = (NR + TB - 1) / TB;

    wprep_kernel<<<RR, 256>>>(W1, 0);
    wprep_kernel<<<RR, 256>>>(W2, 1);
    zero2_kernel<<<nr_blocks, TB>>>();
    count2_kernel<<<edge_blocks, TB>>>(dst, et);
    scanA_kernel<<<SCAN_BLKS, 1024>>>();
    scanB_kernel<<<1, 1024>>>();
    scanC_kernel<<<nr_blocks, TB>>>();
    scatter2_kernel<<<edge_blocks, TB>>>(src, dst, et);

    layer_kernel<<<NTILES, 256, SMEM_LAYER>>>(h, 0, h1, 1);
    layer_kernel<<<NTILES, 256, SMEM_LAYER>>>(h1, 1, out, 0);

    mean_kernel<<<512, 256>>>(out);
    mlp_kernel<<<1, 64>>>(A1w, A1b, A2w, A2b, out);
}

// round 16
// speedup vs baseline: 1.2836x; 1.2836x over previous
#include <cuda_runtime.h>
#include <cuda_bf16.h>
#include <cstdint>

#define NN 100000
#define EE 3200000
#define RR 20
#define DD 64
#define NR (NN * RR)
#define SCAN_ELEMS 2048
#define SCAN_BLKS ((NR + SCAN_ELEMS - 1) / SCAN_ELEMS)

#define TILE_M 128
#define NTILES ((NN + TILE_M - 1) / TILE_M)   // 782
#define APAD 72
#define A_BYTES (TILE_M * APAD * 2)           // 18432
#define B_BYTES (64 * APAD * 2)               // 9216
#define SMEM_LAYER (2 * A_BYTES + 2 * B_BYTES) // 55296

// ---------------- scratch ----------------
__device__ float g_h1[(size_t)NN * DD];
__device__ int   g_cnt2[NR];
__device__ int   g_cursor2[NR];
__device__ int   g_rowoff2[NR + 1];
__device__ int   g_part[1024];
__device__ int   g_sorted[EE];
__device__ float g_gsum[DD];
__device__ __nv_bfloat16 g_Bhi[2][RR * 64 * APAD];
__device__ __nv_bfloat16 g_Blo[2][RR * 64 * APAD];

// ---------------- prep: counting sort by (dst*RR + etype) ----------------
__global__ void zero2_kernel() {
    int i = blockIdx.x * blockDim.x + threadIdx.x;
    int stride = gridDim.x * blockDim.x;
    for (; i < NR; i += stride) g_cnt2[i] = 0;
    if (blockIdx.x == 0 && threadIdx.x < DD) g_gsum[threadIdx.x] = 0.0f;
}
__global__ void count2_kernel(const int* __restrict__ dst, const int* __restrict__ et) {
    int i = blockIdx.x * blockDim.x + threadIdx.x;
    int stride = gridDim.x * blockDim.x;
    for (; i < EE; i += stride) atomicAdd(&g_cnt2[dst[i] * RR + et[i]], 1);
}
__global__ __launch_bounds__(1024) void scanA_kernel() {
    __shared__ int wsum[32];
    const int tid = threadIdx.x, lane = tid & 31, wid = tid >> 5;
    int i0 = blockIdx.x * SCAN_ELEMS + tid * 2;
    int v0 = (i0 < NR) ? g_cnt2[i0] : 0;
    int v1 = (i0 + 1 < NR) ? g_cnt2[i0 + 1] : 0;
    int tsum = v0 + v1, x = tsum;
    #pragma unroll
    for (int off = 1; off < 32; off <<= 1) {
        int y = __shfl_up_sync(0xFFFFFFFFu, x, off);
        if (lane >= off) x += y;
    }
    if (lane == 31) wsum[wid] = x;
    __syncthreads();
    if (wid == 0) {
        int w = wsum[lane];
        #pragma unroll
        for (int off = 1; off < 32; off <<= 1) {
            int y = __shfl_up_sync(0xFFFFFFFFu, w, off);
            if (lane >= off) w += y;
        }
        wsum[lane] = w;
    }
    __syncthreads();
    int excl = x - tsum + (wid ? wsum[wid - 1] : 0);
    if (i0 < NR) g_rowoff2[i0] = excl;
    if (i0 + 1 < NR) g_rowoff2[i0 + 1] = excl + v0;
    if (tid == 0) g_part[blockIdx.x] = wsum[31];
}
__global__ __launch_bounds__(1024) void scanB_kernel() {
    __shared__ int wsum[32];
    const int tid = threadIdx.x, lane = tid & 31, wid = tid >> 5;
    int v = (tid < SCAN_BLKS) ? g_part[tid] : 0;
    int x = v;
    #pragma unroll
    for (int off = 1; off < 32; off <<= 1) {
        int y = __shfl_up_sync(0xFFFFFFFFu, x, off);
        if (lane >= off) x += y;
    }
    if (lane == 31) wsum[wid] = x;
    __syncthreads();
    if (wid == 0) {
        int w = wsum[lane];
        #pragma unroll
        for (int off = 1; off < 32; off <<= 1) {
            int y = __shfl_up_sync(0xFFFFFFFFu, w, off);
            if (lane >= off) w += y;
        }
        wsum[lane] = w;
    }
    __syncthreads();
    g_part[tid] = x - v + (wid ? wsum[wid - 1] : 0);
}
__global__ void scanC_kernel() {
    int i = blockIdx.x * blockDim.x + threadIdx.x;
    int stride = gridDim.x * blockDim.x;
    for (; i < NR; i += stride) {
        int v = g_rowoff2[i] + g_part[i >> 11];
        g_rowoff2[i] = v;
        g_cursor2[i] = v;
    }
    if (blockIdx.x == 0 && threadIdx.x == 0) g_rowoff2[NR] = EE;
}
__global__ void scatter2_kernel(const int* __restrict__ src,
                                const int* __restrict__ dst,
                                const int* __restrict__ et) {
    int i = blockIdx.x * blockDim.x + threadIdx.x;
    int stride = gridDim.x * blockDim.x;
    for (; i < EE; i += stride) {
        int pos = atomicAdd(&g_cursor2[dst[i] * RR + et[i]], 1);
        g_sorted[pos] = src[i];
    }
}

// ---------------- W prep: transpose + bf16 hi/lo split ----------------
__global__ void wprep_kernel(const float* __restrict__ W, int slot) {
    int r = blockIdx.x;
    for (int idx = threadIdx.x; idx < 4096; idx += blockDim.x) {
        int o = idx >> 6, d = idx & 63;
        float v = W[r * 4096 + d * 64 + o];
        __nv_bfloat16 hi = __float2bfloat16(v);
        float rest = v - __bfloat162float(hi);
        g_Bhi[slot][r * 64 * APAD + o * APAD + d] = hi;
        g_Blo[slot][r * 64 * APAD + o * APAD + d] = __float2bfloat16(rest);
    }
}

// ---------------- fused layer ----------------
static __device__ __forceinline__ void mma_bf16(float* c, const uint32_t* a, const uint32_t* b) {
    asm volatile(
        "mma.sync.aligned.m16n8k16.row.col.f32.bf16.bf16.f32 "
        "{%0,%1,%2,%3}, {%4,%5,%6,%7}, {%8,%9}, {%0,%1,%2,%3};"
        : "+f"(c[0]), "+f"(c[1]), "+f"(c[2]), "+f"(c[3])
        : "r"(a[0]), "r"(a[1]), "r"(a[2]), "r"(a[3]), "r"(b[0]), "r"(b[1]));
}

__global__ void __launch_bounds__(256, 3)
layer_kernel(const float* __restrict__ in, int slot, float* __restrict__ out, int relu) {
    extern __shared__ __align__(16) char sm[];
    char* AH = sm;                         // [128][APAD] bf16
    char* AL = AH + A_BYTES;
    char* BH = AL + A_BYTES;               // [64][APAD] bf16 (W^T)
    char* BL = BH + B_BYTES;

    const int tid = threadIdx.x;
    const int node0 = blockIdx.x * TILE_M;
    const int hw = tid >> 4;       // 0..15 half-warp
    const int l4 = tid & 15;       // feature quad
    const int wid = tid >> 5;      // 0..7
    const int lane = tid & 31;
    const int g = lane >> 2;       // 0..7
    const int tg = lane & 3;       // 0..3
    const int R0 = wid * 16;

    float c[8][4];
    #pragma unroll
    for (int i = 0; i < 8; i++)
        #pragma unroll
        for (int j = 0; j < 4; j++) c[i][j] = 0.f;

    const __nv_bfloat16* Bh = g_Bhi[slot];
    const __nv_bfloat16* Bl = g_Blo[slot];

    for (int r = 0; r < RR; r++) {
        // ---- B copy ----
        {
            const uint4* bs = (const uint4*)(Bh + (size_t)r * 64 * APAD);
            const uint4* ls = (const uint4*)(Bl + (size_t)r * 64 * APAD);
            uint4* bd = (uint4*)BH;
            uint4* ld = (uint4*)BL;
            for (int i = tid; i < 576; i += 256) { bd[i] = bs[i]; ld[i] = ls[i]; }
        }
        // ---- gather: half-warp per node, 8 buckets in 2 batched groups of 4 ----
        #pragma unroll
        for (int gq = 0; gq < 2; gq++) {
            int sarr[4], larr[4];
            // phase 1: all offsets in flight
            #pragma unroll
            for (int q = 0; q < 4; q++) {
                int node = node0 + hw + (gq * 4 + q) * 16;
                if (node < NN) {
                    int key = node * RR + r;
                    int s0 = g_rowoff2[key];
                    sarr[q] = s0;
                    larr[q] = g_rowoff2[key + 1] - s0;
                } else { sarr[q] = 0; larr[q] = 0; }
            }
            // phase 2: first-2 edge indices of each bucket in flight
            int i0[4], i1[4];
            #pragma unroll
            for (int q = 0; q < 4; q++) {
                i0[q] = (larr[q] > 0) ? g_sorted[sarr[q]] : 0;
                i1[q] = (larr[q] > 1) ? g_sorted[sarr[q] + 1] : 0;
            }
            // phase 3: corresponding h-rows, independent accumulators
            float4 acc[4];
            #pragma unroll
            for (int q = 0; q < 4; q++) {
                acc[q] = make_float4(0.f, 0.f, 0.f, 0.f);
                if (larr[q] > 0) {
                    const float4 v = *(const float4*)(in + (size_t)i0[q] * 64 + l4 * 4);
                    acc[q].x += v.x; acc[q].y += v.y; acc[q].z += v.z; acc[q].w += v.w;
                }
                if (larr[q] > 1) {
                    const float4 v = *(const float4*)(in + (size_t)i1[q] * 64 + l4 * 4);
                    acc[q].x += v.x; acc[q].y += v.y; acc[q].z += v.z; acc[q].w += v.w;
                }
            }
            // phase 4: residual edges (buckets with >2)
            #pragma unroll
            for (int q = 0; q < 4; q++) {
                int e = sarr[q] + larr[q];
                for (int i = sarr[q] + 2; i < e; i++) {
                    int sv = g_sorted[i];
                    const float4 v = *(const float4*)(in + (size_t)sv * 64 + l4 * 4);
                    acc[q].x += v.x; acc[q].y += v.y; acc[q].z += v.z; acc[q].w += v.w;
                }
            }
            // convert + store to smem (split bf16)
            #pragma unroll
            for (int q = 0; q < 4; q++) {
                int nn = hw + (gq * 4 + q) * 16;
                __nv_bfloat162 h01 = __floats2bfloat162_rn(acc[q].x, acc[q].y);
                __nv_bfloat162 h23 = __floats2bfloat162_rn(acc[q].z, acc[q].w);
                float2 f01 = __bfloat1622float2(h01);
                float2 f23 = __bfloat1622float2(h23);
                __nv_bfloat162 l01 = __floats2bfloat162_rn(acc[q].x - f01.x, acc[q].y - f01.y);
                __nv_bfloat162 l23 = __floats2bfloat162_rn(acc[q].z - f23.x, acc[q].w - f23.y);
                uint32_t off = (uint32_t)(nn * APAD + l4 * 4) * 2;
                *(uint2*)(AH + off) = make_uint2(*(uint32_t*)&h01, *(uint32_t*)&h23);
                *(uint2*)(AL + off) = make_uint2(*(uint32_t*)&l01, *(uint32_t*)&l23);
            }
        }
        __syncthreads();

        // ---- MMA: warp computes rows [R0, R0+16) x 64 cols ----
        #pragma unroll
        for (int kc = 0; kc < 4; kc++) {
            const int kb = kc * 16;
            uint32_t ah[4], al[4];
            {
                uint32_t o0 = (uint32_t)((R0 + g) * APAD + kb + tg * 2) * 2;
                uint32_t o1 = (uint32_t)((R0 + g + 8) * APAD + kb + tg * 2) * 2;
                ah[0] = *(const uint32_t*)(AH + o0);
                ah[1] = *(const uint32_t*)(AH + o1);
                ah[2] = *(const uint32_t*)(AH + o0 + 16);
                ah[3] = *(const uint32_t*)(AH + o1 + 16);
                al[0] = *(const uint32_t*)(AL + o0);
                al[1] = *(const uint32_t*)(AL + o1);
                al[2] = *(const uint32_t*)(AL + o0 + 16);
                al[3] = *(const uint32_t*)(AL + o1 + 16);
            }
            #pragma unroll
            for (int nt = 0; nt < 8; nt++) {
                uint32_t bh[2], bl[2];
                uint32_t ob = (uint32_t)((nt * 8 + g) * APAD + kb + tg * 2) * 2;
                bh[0] = *(const uint32_t*)(BH + ob);
                bh[1] = *(const uint32_t*)(BH + ob + 16);
                bl[0] = *(const uint32_t*)(BL + ob);
                bl[1] = *(const uint32_t*)(BL + ob + 16);
                mma_bf16(c[nt], ah, bh);
                mma_bf16(c[nt], ah, bl);
                mma_bf16(c[nt], al, bh);
            }
        }
        __syncthreads();
    }

    // ---- epilogue ----
    int row_a = node0 + R0 + g;
    int row_b = row_a + 8;
    #pragma unroll
    for (int nt = 0; nt < 8; nt++) {
        float v0 = c[nt][0], v1 = c[nt][1], v2 = c[nt][2], v3 = c[nt][3];
        if (relu) {
            v0 = fmaxf(v0, 0.f); v1 = fmaxf(v1, 0.f);
            v2 = fmaxf(v2, 0.f); v3 = fmaxf(v3, 0.f);
        }
        int col = nt * 8 + tg * 2;
        if (row_a < NN) *(float2*)(out + (size_t)row_a * 64 + col) = make_float2(v0, v1);
        if (row_b < NN) *(float2*)(out + (size_t)row_b * 64 + col) = make_float2(v2, v3);
    }
}

// ---------------- graph mean + attributor MLP ----------------
__global__ void mean_kernel(const float* __restrict__ h2) {
    int dim = threadIdx.x & 63;
    int rgrp = threadIdx.x >> 6;
    float acc = 0.f;
    for (int row = blockIdx.x * 4 + rgrp; row < NN; row += gridDim.x * 4)
        acc += h2[(size_t)row * 64 + dim];
    __shared__ float s[256];
    s[threadIdx.x] = acc;
    __syncthreads();
    if (threadIdx.x < 64) {
        float v = s[threadIdx.x] + s[threadIdx.x + 64] + s[threadIdx.x + 128] + s[threadIdx.x + 192];
        atomicAdd(&g_gsum[threadIdx.x], v);
    }
}
__global__ void mlp_kernel(const float* __restrict__ A1w, const float* __restrict__ A1b,
                           const float* __restrict__ A2w, const float* __restrict__ A2b,
                           float* __restrict__ out) {
    __shared__ float g[64];
    __shared__ float hid[32];
    int tid = threadIdx.x;
    if (tid < 64) g[tid] = g_gsum[tid] * (1.0f / (float)NN);
    __syncthreads();
    if (tid < 32) {
        float s = A1b[tid];
        #pragma unroll
        for (int k = 0; k < 64; k++) s += g[k] * A1w[k * 32 + tid];
        hid[tid] = fmaxf(s, 0.f);
    }
    __syncthreads();
    if (tid < 10) {
        float s = A2b[tid];
        #pragma unroll
        for (int k = 0; k < 32; k++) s += hid[k] * A2w[k * 10 + tid];
        out[(size_t)NN * 64 + tid] = 1.0f / (1.0f + expf(-s));
    }
}

// ---------------- launch ----------------
extern "C" void kernel_launch(void* const* d_in, const int* in_sizes, int n_in,
                              void* d_out, int out_size) {
    const float* h   = (const float*)d_in[0];
    const int*   src = (const int*)d_in[1];
    const int*   dst = (const int*)d_in[2];
    const int*   et  = (const int*)d_in[3];
    const float* W1  = (const float*)d_in[4];
    const float* W2  = (const float*)d_in[5];
    const float* A1w = (const float*)d_in[6];
    const float* A1b = (const float*)d_in[7];
    const float* A2w = (const float*)d_in[8];
    const float* A2b = (const float*)d_in[9];
    float* out = (float*)d_out;

    void* h1_ptr = nullptr;
    cudaGetSymbolAddress(&h1_ptr, g_h1);
    float* h1 = (float*)h1_ptr;

    static bool attr_done = false;
    if (!attr_done) {
        cudaFuncSetAttribute(layer_kernel, cudaFuncAttributeMaxDynamicSharedMemorySize, SMEM_LAYER);
        attr_done = true;
    }

    const int TB = 256;
    const int edge_blocks = (EE + TB - 1) / TB;
    const int nr_blocks = (NR + TB - 1) / TB;

    wprep_kernel<<<RR, 256>>>(W1, 0);
    wprep_kernel<<<RR, 256>>>(W2, 1);
    zero2_kernel<<<nr_blocks, TB>>>();
    count2_kernel<<<edge_blocks, TB>>>(dst, et);
    scanA_kernel<<<SCAN_BLKS, 1024>>>();
    scanB_kernel<<<1, 1024>>>();
    scanC_kernel<<<nr_blocks, TB>>>();
    scatter2_kernel<<<edge_blocks, TB>>>(src, dst, et);

    layer_kernel<<<NTILES, 256, SMEM_LAYER>>>(h, 0, h1, 1);
    layer_kernel<<<NTILES, 256, SMEM_LAYER>>>(h1, 1, out, 0);

    mean_kernel<<<512, 256>>>(out);
    mlp_kernel<<<1, 64>>>(A1w, A1b, A2w, A2b, out);
}